// round 3
// baseline (speedup 1.0000x reference)
#include <cuda_runtime.h>
#include <cstdint>

// MixtureCrossattention: per batch b,
//   C = [e1 | e2]  (16 x 576),  e = patch_embed(x)
//   x3[:,q] = sum_p lam3(p) * softmax_p(e2[:,q]·C[:,p]) * C[:,p]   (lam3 = 0.7 for p<288 else 0.3)
//   x4[:,q] = sum_p lam4(p) * softmax_p(e1[:,q]·C[:,p]) * C[:,p]   (lam4 = 0.3 for p<288 else 0.7)
// (the reference's batch-0 block-transpose is a no-op: the e2^T e2 block is symmetric)
//
// One CTA per (batch, half), 288 threads, one query per thread.
// sK layout: row per key column j (0..575), 16 dims = 64B. f32x2 lanes = adjacent dims.
// Keys are loaded from smem ONCE per column and reused for score + accumulate.
// lambda folded into the exponent bias: w = 2^(s*log2e + log2(lam)) = lam*e^s.

#define LOG2E   1.4426950408889634f
#define LOG2_07 (-0.5145731728297583f)
#define LOG2_03 (-1.7369655941662063f)

typedef unsigned long long ull;

__device__ __forceinline__ ull pack2(float lo, float hi) {
    ull r; asm("mov.b64 %0, {%1, %2};" : "=l"(r) : "f"(lo), "f"(hi)); return r;
}
__device__ __forceinline__ void unpack2(ull v, float &lo, float &hi) {
    asm("mov.b64 {%0, %1}, %2;" : "=f"(lo), "=f"(hi) : "l"(v));
}
__device__ __forceinline__ ull fma2(ull a, ull b, ull c) {
    ull d; asm("fma.rn.f32x2 %0, %1, %2, %3;" : "=l"(d) : "l"(a), "l"(b), "l"(c)); return d;
}
__device__ __forceinline__ ull add2(ull a, ull b) {
    ull d; asm("add.rn.f32x2 %0, %1, %2;" : "=l"(d) : "l"(a), "l"(b)); return d;
}
__device__ __forceinline__ float ex2a(float x) {
    float y; asm("ex2.approx.f32 %0, %1;" : "=f"(y) : "f"(x)); return y;
}

__global__ __launch_bounds__(288, 2)
void mixca_kernel(const float* __restrict__ x1,
                  const float* __restrict__ x2,
                  float* __restrict__ out)
{
    // sK[j*16 + i] = C[i][j], j = key column 0..575, i = dim 0..15
    __shared__ __align__(16) float sK[576 * 16];

    const int b    = blockIdx.x;
    const int half = blockIdx.y;   // 0 -> x3, 1 -> x4
    const int t    = threadIdx.x;  // query 0..287

    // ---- Load + patch-embed both inputs into sK ----
    {
        const float* src0 = x1 + (size_t)b * 4608;
        const float* src1 = x2 + (size_t)b * 4608;
        #pragma unroll
        for (int e = 0; e < 2; e++) {
            const float* src = (e == 0) ? src0 : src1;
            #pragma unroll
            for (int k = 0; k < 16; k++) {
                int g = t + k * 288;           // linear idx into [32][12][12]
                float v = src[g];
                int c   = g / 144;
                int rem = g - c * 144;
                int r   = rem / 12;
                int s   = rem - r * 12;
                int h = r / 3, p1 = r - h * 3;
                int w = s / 3, p2 = s - w * 3;
                int i = h * 4 + w;                        // 0..15
                int j = (p1 * 3 + p2) * 32 + c + e * 288; // 0..575
                sK[j * 16 + i] = v;
            }
        }
    }
    __syncthreads();

    // ---- Query vector: dims packed in pairs, pre-scaled by log2(e) ----
    const int qcol = (half == 0) ? (288 + t) : t;   // x3 uses e2 queries, x4 uses e1
    ull qv[8];
    {
        const float4* qp = reinterpret_cast<const float4*>(&sK[qcol * 16]);
        #pragma unroll
        for (int u = 0; u < 4; u++) {
            float4 q = qp[u];
            qv[2 * u]     = pack2(q.x * LOG2E, q.y * LOG2E);
            qv[2 * u + 1] = pack2(q.z * LOG2E, q.w * LOG2E);
        }
    }

    ull acc[8];
    #pragma unroll
    for (int i = 0; i < 8; i++) acc[i] = 0ull;
    float sw0 = 0.0f, sw1 = 0.0f;   // lam-weighted sums per segment

    const float biasA = (half == 0) ? LOG2_07 : LOG2_03;  // keys 0..287
    const float biasB = (half == 0) ? LOG2_03 : LOG2_07;  // keys 288..575

    #pragma unroll
    for (int seg = 0; seg < 2; seg++) {
        const ull bias2 = pack2(seg ? biasB : biasA, 0.0f);
        float swseg = 0.0f;
        #pragma unroll 1
        for (int jp = seg * 144; jp < seg * 144 + 144; jp++) {
            // two key columns (2jp, 2jp+1): 32 contiguous floats, loaded ONCE
            const ulonglong2* row = reinterpret_cast<const ulonglong2*>(&sK[jp * 32]);
            ulonglong2 a0 = row[0], a1 = row[1], a2 = row[2], a3 = row[3];
            ulonglong2 b0 = row[4], b1 = row[5], b2 = row[6], b3 = row[7];

            // scores (bias = log2 lam folded in; lands once via the lo lane)
            ull sA = fma2(qv[0], a0.x, bias2);
            ull sB = fma2(qv[0], b0.x, bias2);
            sA = fma2(qv[1], a0.y, sA);  sB = fma2(qv[1], b0.y, sB);
            sA = fma2(qv[2], a1.x, sA);  sB = fma2(qv[2], b1.x, sB);
            sA = fma2(qv[3], a1.y, sA);  sB = fma2(qv[3], b1.y, sB);
            sA = fma2(qv[4], a2.x, sA);  sB = fma2(qv[4], b2.x, sB);
            sA = fma2(qv[5], a2.y, sA);  sB = fma2(qv[5], b2.y, sB);
            sA = fma2(qv[6], a3.x, sA);  sB = fma2(qv[6], b3.x, sB);
            sA = fma2(qv[7], a3.y, sA);  sB = fma2(qv[7], b3.y, sB);

            float alo, ahi, blo, bhi;
            unpack2(sA, alo, ahi);
            unpack2(sB, blo, bhi);
            float wA = ex2a(alo + ahi);   // = lam * e^{score_A}
            float wB = ex2a(blo + bhi);
            swseg += wA;
            swseg += wB;
            ull wA2 = pack2(wA, wA);
            ull wB2 = pack2(wB, wB);

            acc[0] = fma2(wA2, a0.x, acc[0]);  acc[0] = fma2(wB2, b0.x, acc[0]);
            acc[1] = fma2(wA2, a0.y, acc[1]);  acc[1] = fma2(wB2, b0.y, acc[1]);
            acc[2] = fma2(wA2, a1.x, acc[2]);  acc[2] = fma2(wB2, b1.x, acc[2]);
            acc[3] = fma2(wA2, a1.y, acc[3]);  acc[3] = fma2(wB2, b1.y, acc[3]);
            acc[4] = fma2(wA2, a2.x, acc[4]);  acc[4] = fma2(wB2, b2.x, acc[4]);
            acc[5] = fma2(wA2, a2.y, acc[5]);  acc[5] = fma2(wB2, b2.y, acc[5]);
            acc[6] = fma2(wA2, a3.x, acc[6]);  acc[6] = fma2(wB2, b3.x, acc[6]);
            acc[7] = fma2(wA2, a3.y, acc[7]);  acc[7] = fma2(wB2, b3.y, acc[7]);
        }
        if (seg == 0) sw0 = swseg; else sw1 = swseg;
    }

    // denominator: sum e^s = sw0/lamA + sw1/lamB
    const float invLamA = (half == 0) ? (1.0f / 0.7f) : (1.0f / 0.3f);
    const float invLamB = (half == 0) ? (1.0f / 0.3f) : (1.0f / 0.7f);
    const float inv = 1.0f / (sw0 * invLamA + sw1 * invLamB);

    __syncthreads();          // everyone done reading sK; reuse as staging
    float* sO = sK;           // [288][17] padded
    #pragma unroll
    for (int u = 0; u < 8; u++) {
        float lo, hi;
        unpack2(acc[u], lo, hi);
        sO[t * 17 + 2 * u]     = lo * inv;
        sO[t * 17 + 2 * u + 1] = hi * inv;
    }
    __syncthreads();

    // ---- Coalesced un-patch store: out layout (x3 block, then x4 block) ----
    float* dst = out + ((size_t)half * 512 + (size_t)b) * 4608;
    #pragma unroll
    for (int k = 0; k < 16; k++) {
        int g = t + k * 288;
        int c   = g / 144;
        int rem = g - c * 144;
        int r   = rem / 12;
        int s   = rem - r * 12;
        int h = r / 3, p1 = r - h * 3;
        int w = s / 3, p2 = s - w * 3;
        int i  = h * 4 + w;
        int tt = (p1 * 3 + p2) * 32 + c;
        dst[g] = sO[tt * 17 + i];
    }
}

extern "C" void kernel_launch(void* const* d_in, const int* in_sizes, int n_in,
                              void* d_out, int out_size)
{
    const float* x1 = (const float*)d_in[0];
    const float* x2 = (const float*)d_in[1];
    float* out = (float*)d_out;
    dim3 grid(512, 2);
    mixca_kernel<<<grid, 288>>>(x1, x2, out);
}